// round 7
// baseline (speedup 1.0000x reference)
#include <cuda_runtime.h>
#include <cstdint>

#define N_NODES 100000
#define N_EDGES 1600000
#define IN_C    128
#define HID_C   128
#define OUT_C   64

// ---------------- scratch: device globals (device-code references only) -----
__device__ int    g_is64;
__device__ int    g_degcnt[N_NODES];
__device__ float  g_dinv  [N_NODES];
__device__ int    g_rowptr[N_NODES + 1];
__device__ int    g_cursor[N_NODES];
__device__ int    g_esrc  [N_EDGES];                       // CSR: source node per incoming edge
__device__ float4 g_h1  [(size_t)N_NODES * HID_C / 4];     // X @ W1
__device__ float4 g_agg1[(size_t)N_NODES * HID_C / 4];     // conv1 accumulation
__device__ float4 g_h2  [(size_t)N_NODES * OUT_C / 4];     // relu(agg1) @ W2

// ---------------- edge_index dtype detection (int32 vs int64) ---------------
// int64 little-endian: odd 32-bit words are high words == 0 (ids < 2^31).
// int32: odd words are random node ids; 64 consecutive zeros is impossible.
__global__ void detect_kernel(const unsigned* __restrict__ ei_raw) {
    int zeros = 0;
    for (int i = 0; i < 64; i++)
        if (ei_raw[2 * i + 1] == 0u) zeros++;
    g_is64 = (zeros == 64) ? 1 : 0;
}

__device__ __forceinline__ int edge_row(const void* ei, int e) {
    return g_is64 ? (int)((const long long*)ei)[e] : ((const int*)ei)[e];
}
__device__ __forceinline__ int edge_col(const void* ei, int e) {
    return g_is64 ? (int)((const long long*)ei)[N_EDGES + e]
                  : ((const int*)ei)[N_EDGES + e];
}

// ---------------- degree histogram / norm -----------------------------------
__global__ void zero_cnt_kernel() {
    int i = blockIdx.x * blockDim.x + threadIdx.x;
    if (i < N_NODES) g_degcnt[i] = 0;
}

__global__ void hist_kernel(const void* __restrict__ ei) {
    int e = blockIdx.x * blockDim.x + threadIdx.x;
    if (e < N_EDGES) {
        int c = edge_col(ei, e);
        if ((unsigned)c < (unsigned)N_NODES)
            atomicAdd(&g_degcnt[c], 1);
    }
}

__global__ void dinv_kernel() {
    int i = blockIdx.x * blockDim.x + threadIdx.x;
    if (i < N_NODES) g_dinv[i] = rsqrtf((float)g_degcnt[i] + 1.0f);
}

// ---------------- single-block prefix scan -> rowptr, cursor ----------------
#define SCAN_T 1024
__global__ void scan_kernel() {
    __shared__ int partial[SCAN_T];
    int t = threadIdx.x;
    const int CH = (N_NODES + SCAN_T - 1) / SCAN_T;   // 98
    int beg = t * CH;
    int end = min(beg + CH, N_NODES);
    int s = 0;
    for (int i = beg; i < end; i++) s += g_degcnt[i];
    partial[t] = s;
    __syncthreads();
    for (int off = 1; off < SCAN_T; off <<= 1) {
        int v = (t >= off) ? partial[t - off] : 0;
        __syncthreads();
        partial[t] += v;
        __syncthreads();
    }
    int run = (t == 0) ? 0 : partial[t - 1];
    for (int i = beg; i < end; i++) {
        g_rowptr[i] = run;
        g_cursor[i] = run;
        run += g_degcnt[i];
    }
    if (t == SCAN_T - 1) g_rowptr[N_NODES] = run;
}

// ---------------- CSR fill ---------------------------------------------------
__global__ void fill_kernel(const void* __restrict__ ei) {
    int e = blockIdx.x * blockDim.x + threadIdx.x;
    if (e < N_EDGES) {
        int r = edge_row(ei, e);
        int c = edge_col(ei, e);
        if ((unsigned)c < (unsigned)N_NODES) {
            int pos = atomicAdd(&g_cursor[c], 1);
            g_esrc[pos] = ((unsigned)r < (unsigned)N_NODES) ? r : 0;
        }
    }
}

// ---------------- SGEMM body with fused self-loop epilogue ------------------
// A [M,128] row-major, W [128,BN] row-major.
// H = op(A)@W  (op = relu if RELU_IN, applied to A on load)
// AGG = H * dinv[m]^2 + bias    (self-loop init; gather adds neighbor terms)
template<int BN, bool RELU_IN>
__device__ __forceinline__ void gemm_body(const float* __restrict__ A,
                                          const float* __restrict__ W,
                                          const float* __restrict__ bias,
                                          float* __restrict__ H,
                                          float* __restrict__ AGG) {
    constexpr int BM = 128, BK = 8, TM = 8, TN = 8, K = 128;
    constexpr int TCOLS = BN / TN;            // 16 (BN=128) or 8 (BN=64)
    constexpr int NT    = TCOLS * (BM / TM);  // 256 or 128 threads

    __shared__ float As[BK][BM];
    __shared__ float Bs[BK][BN];

    const int tid  = threadIdx.x;
    const int tRow = tid / TCOLS;
    const int tCol = tid % TCOLS;
    const int m0   = blockIdx.x * BM;

    float acc[TM][TN];
#pragma unroll
    for (int i = 0; i < TM; i++)
#pragma unroll
        for (int j = 0; j < TN; j++) acc[i][j] = 0.0f;

    constexpr int LOADS_A = (BM * BK) / (NT * 4);   // 1 (NT=256) or 2 (NT=128)
    constexpr int LOADS_B = (BK * BN) / (NT * 4);   // 1

    for (int k0 = 0; k0 < K; k0 += BK) {
#pragma unroll
        for (int i = 0; i < LOADS_A; i++) {
            int idx = tid + i * NT;                 // float4 slot 0..255
            int ar  = idx >> 1;
            int ak  = (idx & 1) * 4;
            float4 v = make_float4(0.f, 0.f, 0.f, 0.f);
            int m = m0 + ar;
            if (m < N_NODES)
                v = *(const float4*)(A + (size_t)m * K + k0 + ak);
            if (RELU_IN) {
                v.x = fmaxf(v.x, 0.f); v.y = fmaxf(v.y, 0.f);
                v.z = fmaxf(v.z, 0.f); v.w = fmaxf(v.w, 0.f);
            }
            As[ak + 0][ar] = v.x;
            As[ak + 1][ar] = v.y;
            As[ak + 2][ar] = v.z;
            As[ak + 3][ar] = v.w;
        }
#pragma unroll
        for (int i = 0; i < LOADS_B; i++) {
            int idx = tid + i * NT;
            int bk  = idx / (BN / 4);
            int bn  = (idx % (BN / 4)) * 4;
            *(float4*)&Bs[bk][bn] = *(const float4*)(W + (size_t)(k0 + bk) * BN + bn);
        }
        __syncthreads();

#pragma unroll
        for (int kk = 0; kk < BK; kk++) {
            float a[TM], b[TN];
#pragma unroll
            for (int i = 0; i < TM; i++) a[i] = As[kk][tRow * TM + i];
#pragma unroll
            for (int j = 0; j < TN; j++) b[j] = Bs[kk][tCol * TN + j];
#pragma unroll
            for (int i = 0; i < TM; i++)
#pragma unroll
                for (int j = 0; j < TN; j++) acc[i][j] = fmaf(a[i], b[j], acc[i][j]);
        }
        __syncthreads();
    }

#pragma unroll
    for (int i = 0; i < TM; i++) {
        int m = m0 + tRow * TM + i;
        if (m >= N_NODES) continue;
        float di = g_dinv[m];
        float d2 = di * di;
#pragma unroll
        for (int j = 0; j < TN; j += 4) {
            int n = tCol * TN + j;
            float4 h = make_float4(acc[i][j], acc[i][j + 1], acc[i][j + 2], acc[i][j + 3]);
            *(float4*)(H + (size_t)m * BN + n) = h;
            float4 bi = *(const float4*)(bias + n);
            float4 ag = make_float4(fmaf(h.x, d2, bi.x), fmaf(h.y, d2, bi.y),
                                    fmaf(h.z, d2, bi.z), fmaf(h.w, d2, bi.w));
            *(float4*)(AGG + (size_t)m * BN + n) = ag;
        }
    }
}

__global__ void gemm1_kernel(const float* __restrict__ A,
                             const float* __restrict__ W,
                             const float* __restrict__ bias) {
    gemm_body<128, false>(A, W, bias, (float*)g_h1, (float*)g_agg1);
}

__global__ void gemm2_kernel(const float* __restrict__ W,
                             const float* __restrict__ bias,
                             float* __restrict__ out) {
    gemm_body<64, true>((const float*)g_agg1, W, bias, (float*)g_h2, out);
}

// ---------------- per-node gather over CSR (no atomics) ---------------------
// LPN lanes per node; each lane owns one float4 column slot.
// AGG[c] += sum_{edges (r,c)} dinv[r]*dinv[c] * H[r]
template<int LPN>
__device__ __forceinline__ void gather_body(const float4* __restrict__ H,
                                            float4* __restrict__ AGG) {
    int gtid = blockIdx.x * blockDim.x + threadIdx.x;
    int node = gtid / LPN;
    int lane = gtid % LPN;
    if (node >= N_NODES) return;

    int beg = g_rowptr[node];
    int end = g_rowptr[node + 1];
    float dc = g_dinv[node];

    float4 acc = AGG[(size_t)node * LPN + lane];   // self-loop + bias already there

    for (int j0 = beg; j0 < end; j0 += LPN) {
        int nb = min(LPN, end - j0);
        // batch-prefetch up to LPN edge sources + their dinv, one per lane
        int   r_l = 0;
        float n_l = 0.0f;
        if (lane < nb) {
            r_l = g_esrc[j0 + lane];
            n_l = g_dinv[r_l];
        }
        for (int k = 0; k < nb; k++) {
            int   r  = __shfl_sync(0xffffffffu, r_l, k, LPN);
            float nr = __shfl_sync(0xffffffffu, n_l, k, LPN);
            float s  = nr * dc;
            float4 v = H[(size_t)r * LPN + lane];
            acc.x = fmaf(v.x, s, acc.x);
            acc.y = fmaf(v.y, s, acc.y);
            acc.z = fmaf(v.z, s, acc.z);
            acc.w = fmaf(v.w, s, acc.w);
        }
    }
    AGG[(size_t)node * LPN + lane] = acc;
}

__global__ void gather1_kernel() {                 // g_h1 -> g_agg1 (128 cols)
    gather_body<32>(g_h1, g_agg1);
}

__global__ void gather2_kernel(float4* __restrict__ out) {   // g_h2 -> out (64 cols)
    gather_body<16>(g_h2, out);
}

// ---------------- launch -----------------------------------------------------
extern "C" void kernel_launch(void* const* d_in, const int* in_sizes, int n_in,
                              void* d_out, int out_size) {
    const float* x  = (const float*)d_in[0];
    const void*  ei = d_in[1];                     // int32 or int64, detected on device
    const float* W1 = (const float*)d_in[2];
    const float* b1 = (const float*)d_in[3];
    const float* W2 = (const float*)d_in[4];
    const float* b2 = (const float*)d_in[5];
    float*       out = (float*)d_out;
    (void)in_sizes; (void)n_in; (void)out_size;

    const int T = 256;

    // dtype sniff + CSR build
    detect_kernel  <<<1, 1>>>((const unsigned*)ei);
    zero_cnt_kernel<<<(N_NODES + T - 1) / T, T>>>();
    hist_kernel    <<<(N_EDGES + T - 1) / T, T>>>(ei);
    dinv_kernel    <<<(N_NODES + T - 1) / T, T>>>();
    scan_kernel    <<<1, SCAN_T>>>();
    fill_kernel    <<<(N_EDGES + T - 1) / T, T>>>(ei);

    const int MBLK = (N_NODES + 127) / 128;   // 782

    // layer 1
    gemm1_kernel<<<MBLK, 256>>>(x, W1, b1);
    {
        long long total = (long long)N_NODES * 32;
        gather1_kernel<<<(int)((total + T - 1) / T), T>>>();
    }
    // layer 2
    gemm2_kernel<<<MBLK, 128>>>(W2, b2, out);
    {
        long long total = (long long)N_NODES * 16;
        gather2_kernel<<<(int)((total + T - 1) / T), T>>>((float4*)out);
    }
}

// round 8
// speedup vs baseline: 1.0039x; 1.0039x over previous
#include <cuda_runtime.h>
#include <cstdint>

#define N_NODES 100000
#define N_EDGES 1600000
#define IN_C    128
#define HID_C   128
#define OUT_C   64

// ---------------- scratch: device globals (device-code references only) -----
__device__ int    g_is64;
__device__ int    g_degcnt[N_NODES];
__device__ float  g_dinv  [N_NODES];
__device__ int    g_rowptr[N_NODES + 1];
__device__ int    g_cursor[N_NODES];
__device__ int    g_esrc  [N_EDGES];                       // CSR: source node per incoming edge
__device__ float4 g_h1  [(size_t)N_NODES * HID_C / 4];     // X @ W1
__device__ float4 g_agg1[(size_t)N_NODES * HID_C / 4];     // conv1 accumulation
__device__ float4 g_h2  [(size_t)N_NODES * OUT_C / 4];     // relu(agg1) @ W2

// ---------------- edge_index dtype detection (int32 vs int64) ---------------
// int64 little-endian: odd 32-bit words are high words == 0 (ids < 2^31).
// int32: odd words are random node ids; 64 consecutive zeros is impossible.
__global__ void detect_kernel(const unsigned* __restrict__ ei_raw) {
    int zeros = 0;
    for (int i = 0; i < 64; i++)
        if (ei_raw[2 * i + 1] == 0u) zeros++;
    g_is64 = (zeros == 64) ? 1 : 0;
}

__device__ __forceinline__ int edge_row(const void* ei, int e) {
    return g_is64 ? (int)((const long long*)ei)[e] : ((const int*)ei)[e];
}
__device__ __forceinline__ int edge_col(const void* ei, int e) {
    return g_is64 ? (int)((const long long*)ei)[N_EDGES + e]
                  : ((const int*)ei)[N_EDGES + e];
}

// ---------------- degree histogram / norm -----------------------------------
__global__ void zero_cnt_kernel() {
    int i = blockIdx.x * blockDim.x + threadIdx.x;
    if (i < N_NODES) g_degcnt[i] = 0;
}

__global__ void hist_kernel(const void* __restrict__ ei) {
    int e = blockIdx.x * blockDim.x + threadIdx.x;
    if (e < N_EDGES) {
        int c = edge_col(ei, e);
        if ((unsigned)c < (unsigned)N_NODES)
            atomicAdd(&g_degcnt[c], 1);
    }
}

__global__ void dinv_kernel() {
    int i = blockIdx.x * blockDim.x + threadIdx.x;
    if (i < N_NODES) g_dinv[i] = rsqrtf((float)g_degcnt[i] + 1.0f);
}

// ---------------- single-block prefix scan -> rowptr, cursor ----------------
#define SCAN_T 1024
__global__ void scan_kernel() {
    __shared__ int partial[SCAN_T];
    int t = threadIdx.x;
    const int CH = (N_NODES + SCAN_T - 1) / SCAN_T;   // 98
    int beg = t * CH;
    int end = min(beg + CH, N_NODES);
    int s = 0;
    for (int i = beg; i < end; i++) s += g_degcnt[i];
    partial[t] = s;
    __syncthreads();
    for (int off = 1; off < SCAN_T; off <<= 1) {
        int v = (t >= off) ? partial[t - off] : 0;
        __syncthreads();
        partial[t] += v;
        __syncthreads();
    }
    int run = (t == 0) ? 0 : partial[t - 1];
    for (int i = beg; i < end; i++) {
        g_rowptr[i] = run;
        g_cursor[i] = run;
        run += g_degcnt[i];
    }
    if (t == SCAN_T - 1) g_rowptr[N_NODES] = run;
}

// ---------------- CSR fill ---------------------------------------------------
__global__ void fill_kernel(const void* __restrict__ ei) {
    int e = blockIdx.x * blockDim.x + threadIdx.x;
    if (e < N_EDGES) {
        int r = edge_row(ei, e);
        int c = edge_col(ei, e);
        if ((unsigned)c < (unsigned)N_NODES) {
            int pos = atomicAdd(&g_cursor[c], 1);
            g_esrc[pos] = ((unsigned)r < (unsigned)N_NODES) ? r : 0;
        }
    }
}

// ---------------- SGEMM body with fused self-loop epilogue ------------------
// A [M,128] row-major, W [128,BN] row-major.
// H = op(A)@W  (op = relu if RELU_IN, applied to A on load)
// AGG = H * dinv[m]^2 + bias    (self-loop init; gather adds neighbor terms)
template<int BN, bool RELU_IN>
__device__ __forceinline__ void gemm_body(const float* __restrict__ A,
                                          const float* __restrict__ W,
                                          const float* __restrict__ bias,
                                          float* __restrict__ H,
                                          float* __restrict__ AGG) {
    constexpr int BM = 128, BK = 8, TM = 8, TN = 8, K = 128;
    constexpr int TCOLS = BN / TN;            // 16 (BN=128) or 8 (BN=64)
    constexpr int NT    = TCOLS * (BM / TM);  // 256 or 128 threads

    __shared__ float As[BK][BM];
    __shared__ float Bs[BK][BN];

    const int tid  = threadIdx.x;
    const int tRow = tid / TCOLS;
    const int tCol = tid % TCOLS;
    const int m0   = blockIdx.x * BM;

    float acc[TM][TN];
#pragma unroll
    for (int i = 0; i < TM; i++)
#pragma unroll
        for (int j = 0; j < TN; j++) acc[i][j] = 0.0f;

    constexpr int LOADS_A = (BM * BK) / (NT * 4);   // 1 (NT=256) or 2 (NT=128)
    constexpr int LOADS_B = (BK * BN) / (NT * 4);   // 1

    for (int k0 = 0; k0 < K; k0 += BK) {
#pragma unroll
        for (int i = 0; i < LOADS_A; i++) {
            int idx = tid + i * NT;                 // float4 slot 0..255
            int ar  = idx >> 1;
            int ak  = (idx & 1) * 4;
            float4 v = make_float4(0.f, 0.f, 0.f, 0.f);
            int m = m0 + ar;
            if (m < N_NODES)
                v = *(const float4*)(A + (size_t)m * K + k0 + ak);
            if (RELU_IN) {
                v.x = fmaxf(v.x, 0.f); v.y = fmaxf(v.y, 0.f);
                v.z = fmaxf(v.z, 0.f); v.w = fmaxf(v.w, 0.f);
            }
            As[ak + 0][ar] = v.x;
            As[ak + 1][ar] = v.y;
            As[ak + 2][ar] = v.z;
            As[ak + 3][ar] = v.w;
        }
#pragma unroll
        for (int i = 0; i < LOADS_B; i++) {
            int idx = tid + i * NT;
            int bk  = idx / (BN / 4);
            int bn  = (idx % (BN / 4)) * 4;
            *(float4*)&Bs[bk][bn] = *(const float4*)(W + (size_t)(k0 + bk) * BN + bn);
        }
        __syncthreads();

#pragma unroll
        for (int kk = 0; kk < BK; kk++) {
            float a[TM], b[TN];
#pragma unroll
            for (int i = 0; i < TM; i++) a[i] = As[kk][tRow * TM + i];
#pragma unroll
            for (int j = 0; j < TN; j++) b[j] = Bs[kk][tCol * TN + j];
#pragma unroll
            for (int i = 0; i < TM; i++)
#pragma unroll
                for (int j = 0; j < TN; j++) acc[i][j] = fmaf(a[i], b[j], acc[i][j]);
        }
        __syncthreads();
    }

#pragma unroll
    for (int i = 0; i < TM; i++) {
        int m = m0 + tRow * TM + i;
        if (m >= N_NODES) continue;
        float di = g_dinv[m];
        float d2 = di * di;
#pragma unroll
        for (int j = 0; j < TN; j += 4) {
            int n = tCol * TN + j;
            float4 h = make_float4(acc[i][j], acc[i][j + 1], acc[i][j + 2], acc[i][j + 3]);
            *(float4*)(H + (size_t)m * BN + n) = h;
            float4 bi = *(const float4*)(bias + n);
            float4 ag = make_float4(fmaf(h.x, d2, bi.x), fmaf(h.y, d2, bi.y),
                                    fmaf(h.z, d2, bi.z), fmaf(h.w, d2, bi.w));
            *(float4*)(AGG + (size_t)m * BN + n) = ag;
        }
    }
}

__global__ void gemm1_kernel(const float* __restrict__ A,
                             const float* __restrict__ W,
                             const float* __restrict__ bias) {
    gemm_body<128, false>(A, W, bias, (float*)g_h1, (float*)g_agg1);
}

__global__ void gemm2_kernel(const float* __restrict__ W,
                             const float* __restrict__ bias,
                             float* __restrict__ out) {
    gemm_body<64, true>((const float*)g_agg1, W, bias, (float*)g_h2, out);
}

// ---------------- per-node gather over CSR (no atomics) ---------------------
// LPN lanes per node; each lane owns one float4 column slot.
// AGG[c] += sum_{edges (r,c)} dinv[r]*dinv[c] * H[r]
template<int LPN>
__device__ __forceinline__ void gather_body(const float4* __restrict__ H,
                                            float4* __restrict__ AGG) {
    int gtid = blockIdx.x * blockDim.x + threadIdx.x;
    int node = gtid / LPN;
    int lane = gtid % LPN;
    if (node >= N_NODES) return;

    int beg = g_rowptr[node];
    int end = g_rowptr[node + 1];
    float dc = g_dinv[node];

    float4 acc = AGG[(size_t)node * LPN + lane];   // self-loop + bias already there

    for (int j0 = beg; j0 < end; j0 += LPN) {
        int nb = min(LPN, end - j0);
        // batch-prefetch up to LPN edge sources + their dinv, one per lane
        int   r_l = 0;
        float n_l = 0.0f;
        if (lane < nb) {
            r_l = g_esrc[j0 + lane];
            n_l = g_dinv[r_l];
        }
        for (int k = 0; k < nb; k++) {
            int   r  = __shfl_sync(0xffffffffu, r_l, k, LPN);
            float nr = __shfl_sync(0xffffffffu, n_l, k, LPN);
            float s  = nr * dc;
            float4 v = H[(size_t)r * LPN + lane];
            acc.x = fmaf(v.x, s, acc.x);
            acc.y = fmaf(v.y, s, acc.y);
            acc.z = fmaf(v.z, s, acc.z);
            acc.w = fmaf(v.w, s, acc.w);
        }
    }
    AGG[(size_t)node * LPN + lane] = acc;
}

__global__ void gather1_kernel() {                 // g_h1 -> g_agg1 (128 cols)
    gather_body<32>(g_h1, g_agg1);
}

__global__ void gather2_kernel(float4* __restrict__ out) {   // g_h2 -> out (64 cols)
    gather_body<16>(g_h2, out);
}

// ---------------- launch -----------------------------------------------------
extern "C" void kernel_launch(void* const* d_in, const int* in_sizes, int n_in,
                              void* d_out, int out_size) {
    const float* x  = (const float*)d_in[0];
    const void*  ei = d_in[1];                     // int32 or int64, detected on device
    const float* W1 = (const float*)d_in[2];
    const float* b1 = (const float*)d_in[3];
    const float* W2 = (const float*)d_in[4];
    const float* b2 = (const float*)d_in[5];
    float*       out = (float*)d_out;
    (void)in_sizes; (void)n_in; (void)out_size;

    const int T = 256;

    // dtype sniff + CSR build
    detect_kernel  <<<1, 1>>>((const unsigned*)ei);
    zero_cnt_kernel<<<(N_NODES + T - 1) / T, T>>>();
    hist_kernel    <<<(N_EDGES + T - 1) / T, T>>>(ei);
    dinv_kernel    <<<(N_NODES + T - 1) / T, T>>>();
    scan_kernel    <<<1, SCAN_T>>>();
    fill_kernel    <<<(N_EDGES + T - 1) / T, T>>>(ei);

    const int MBLK = (N_NODES + 127) / 128;   // 782

    // layer 1
    gemm1_kernel<<<MBLK, 256>>>(x, W1, b1);
    {
        long long total = (long long)N_NODES * 32;
        gather1_kernel<<<(int)((total + T - 1) / T), T>>>();
    }
    // layer 2
    gemm2_kernel<<<MBLK, 128>>>(W2, b2, out);
    {
        long long total = (long long)N_NODES * 16;
        gather2_kernel<<<(int)((total + T - 1) / T), T>>>((float4*)out);
    }
}